// round 1
// baseline (speedup 1.0000x reference)
#include <cuda_runtime.h>
#include <cuda_bf16.h>
#include <cstdint>

#define DIM   2048
#define FFN   8192
#define SEQ   2048
#define MROWS 4096      // B*S
#define QKV_N 6144
#define NH    32
#define HD    64
#define EPS   1e-5f

// ---------------- static device scratch (no allocation allowed) ----------------
__device__ __nv_bfloat16 g_Wqkv[(size_t)QKV_N * DIM];
__device__ __nv_bfloat16 g_Wo  [(size_t)DIM   * DIM];
__device__ __nv_bfloat16 g_Win [(size_t)FFN   * DIM];
__device__ __nv_bfloat16 g_W1  [(size_t)DIM   * FFN];
__device__ __nv_bfloat16 g_W2  [(size_t)DIM   * FFN];
__device__ float         g_bqkv[QKV_N];
__device__ float         g_x1 [(size_t)MROWS * DIM];
__device__ __nv_bfloat16 g_h  [(size_t)MROWS * DIM];   // reused: h1 then h2
__device__ float         g_qkv[(size_t)MROWS * QKV_N];
__device__ __nv_bfloat16 g_ctx[(size_t)MROWS * DIM];
__device__ float         g_x2 [(size_t)MROWS * DIM];
__device__ __nv_bfloat16 g_hid[(size_t)MROWS * FFN];
__device__ float         g_a1 [(size_t)MROWS * DIM];
__device__ float         g_a2 [(size_t)MROWS * DIM];

// ---------------- fp32 -> bf16 weight conversion ----------------
__global__ void k_cvt(const float* __restrict__ s, __nv_bfloat16* __restrict__ d, int n4) {
    int i = blockIdx.x * blockDim.x + threadIdx.x;
    if (i < n4) {
        float4 v = ((const float4*)s)[i];
        ((__nv_bfloat162*)d)[2*i]   = __floats2bfloat162_rn(v.x, v.y);
        ((__nv_bfloat162*)d)[2*i+1] = __floats2bfloat162_rn(v.z, v.w);
    }
}

// ---------------- rotary add + rmsnorm (block = one row/token) ----------------
__global__ void k_rot_rms(const float* __restrict__ x, const float* __restrict__ scale,
                          float* __restrict__ x1, __nv_bfloat16* __restrict__ h) {
    int row = blockIdx.x;
    int pos = row & (SEQ - 1);
    const float* xr = x + (size_t)row * DIM;
    const float c = -0.0129762816206537f;  // -log2(10000)/1024
    float vals[8]; float ss = 0.f;
#pragma unroll
    for (int i = 0; i < 8; i++) {
        int d = threadIdx.x + i * 256;
        int j = d & 1023;
        float rot = (float)pos * exp2f(c * (float)j);
        float v = xr[d] + rot;
        vals[i] = v; ss += v * v;
    }
    for (int o = 16; o; o >>= 1) ss += __shfl_xor_sync(~0u, ss, o);
    __shared__ float sred[8];
    if ((threadIdx.x & 31) == 0) sred[threadIdx.x >> 5] = ss;
    __syncthreads();
    float tot = 0.f;
#pragma unroll
    for (int w = 0; w < 8; w++) tot += sred[w];
    float rinv = rsqrtf(tot + EPS);
#pragma unroll
    for (int i = 0; i < 8; i++) {
        int d = threadIdx.x + i * 256;
        x1[(size_t)row * DIM + d] = vals[i];
        h [(size_t)row * DIM + d] = __float2bfloat16(scale[d] * vals[i] * rinv);
    }
}

// ---------------- rmsnorm only ----------------
__global__ void k_rms(const float* __restrict__ x, const float* __restrict__ scale,
                      __nv_bfloat16* __restrict__ h) {
    int row = blockIdx.x;
    const float* xr = x + (size_t)row * DIM;
    float vals[8]; float ss = 0.f;
#pragma unroll
    for (int i = 0; i < 8; i++) {
        int d = threadIdx.x + i * 256;
        float v = xr[d];
        vals[i] = v; ss += v * v;
    }
    for (int o = 16; o; o >>= 1) ss += __shfl_xor_sync(~0u, ss, o);
    __shared__ float sred[8];
    if ((threadIdx.x & 31) == 0) sred[threadIdx.x >> 5] = ss;
    __syncthreads();
    float tot = 0.f;
#pragma unroll
    for (int w = 0; w < 8; w++) tot += sred[w];
    float rinv = rsqrtf(tot + EPS);
#pragma unroll
    for (int i = 0; i < 8; i++) {
        int d = threadIdx.x + i * 256;
        h[(size_t)row * DIM + d] = __float2bfloat16(scale[d] * vals[i] * rinv);
    }
}

// ---------------- per-token attention over heads ----------------
// scores[q,k] = dot(q_head, k_head)/8 per token; softmax over k; ctx = attn @ v
__global__ void k_attn(const float* __restrict__ qkv, __nv_bfloat16* __restrict__ ctx) {
    int t = blockIdx.x;
    __shared__ float sq[NH * HD];        // [h][d]
    __shared__ float sk[NH * (HD + 1)];  // padded rows (65)
    __shared__ float sv[NH * HD];
    const float* base = qkv + (size_t)t * QKV_N;
    for (int i = threadIdx.x; i < DIM; i += 256) {
        sq[i] = base[i];
        sk[(i >> 6) * (HD + 1) + (i & 63)] = base[DIM + i];
        sv[i] = base[2 * DIM + i];
    }
    __syncthreads();
    int warp = threadIdx.x >> 5, lane = threadIdx.x & 31;
    for (int h = warp; h < NH; h += 8) {
        // lane j = kv head j
        float s = 0.f;
#pragma unroll 8
        for (int d = 0; d < HD; d++) s += sq[h * HD + d] * sk[lane * (HD + 1) + d];
        s *= 0.125f;
        float mx = s;
        for (int o = 16; o; o >>= 1) mx = fmaxf(mx, __shfl_xor_sync(~0u, mx, o));
        float e = __expf(s - mx);
        float sum = e;
        for (int o = 16; o; o >>= 1) sum += __shfl_xor_sync(~0u, sum, o);
        float a = e / sum;
        float c0 = 0.f, c1 = 0.f;
#pragma unroll
        for (int j = 0; j < NH; j++) {
            float aj = __shfl_sync(~0u, a, j);
            c0 += aj * sv[j * HD + lane];
            c1 += aj * sv[j * HD + 32 + lane];
        }
        size_t o = (size_t)t * DIM + h * HD;
        ctx[o + lane]      = __float2bfloat16(c0);
        ctx[o + 32 + lane] = __float2bfloat16(c1);
    }
}

// ---------------- bf16 tensor-core GEMM: C[M,N] = A[M,K] @ W[N,K]^T ----------------
#define BM 128
#define BN 128
#define BK 64
#define SMEM_BYTES (2 * (BM + BN) * BK * 2)

__device__ __forceinline__ uint32_t smem_u32(const void* p) {
    return (uint32_t)__cvta_generic_to_shared(p);
}

// OUT_MODE: 0 = fp32 (+bias), 1 = fp32 (+bias+res), 2 = bf16 (+bias)
template <int OUT_MODE>
__global__ __launch_bounds__(256) void gemm_bf16(
    const __nv_bfloat16* __restrict__ A, const __nv_bfloat16* __restrict__ W,
    const float* __restrict__ bias, const float* __restrict__ res,
    void* __restrict__ Cout, int M, int N, int K) {
    extern __shared__ char smem_raw[];
    __nv_bfloat16* sA = (__nv_bfloat16*)smem_raw;           // [2][BM][BK] swizzled
    __nv_bfloat16* sB = sA + 2 * BM * BK;                   // [2][BN][BK] swizzled

    int tid = threadIdx.x;
    int bm = blockIdx.y * BM;
    int bn = blockIdx.x * BN;
    int warp = tid >> 5, lane = tid & 31;
    int wm = (warp >> 2) * 64;    // 0 / 64
    int wn = (warp & 3) * 32;     // 0..96

    float acc[4][4][4];
#pragma unroll
    for (int i = 0; i < 4; i++)
#pragma unroll
        for (int j = 0; j < 4; j++)
#pragma unroll
            for (int r = 0; r < 4; r++) acc[i][j][r] = 0.f;

    const int KT = K / BK;

    auto load_tile = [&](int kt, int buf) {
        const __nv_bfloat16* Ag = A + (size_t)bm * K + kt * BK;
        const __nv_bfloat16* Wg = W + (size_t)bn * K + kt * BK;
        __nv_bfloat16* sAb = sA + buf * BM * BK;
        __nv_bfloat16* sBb = sB + buf * BN * BK;
#pragma unroll
        for (int i = 0; i < 4; i++) {
            int c = tid + i * 256;          // 0..1023
            int row = c >> 3, u = c & 7;    // 16B unit
            uint32_t sa = smem_u32(sAb + row * BK + ((u ^ (row & 7)) << 3));
            const void* ga = Ag + (size_t)row * K + u * 8;
            asm volatile("cp.async.cg.shared.global [%0], [%1], 16;\n" ::"r"(sa), "l"(ga));
            uint32_t sb = smem_u32(sBb + row * BK + ((u ^ (row & 7)) << 3));
            const void* gb = Wg + (size_t)row * K + u * 8;
            asm volatile("cp.async.cg.shared.global [%0], [%1], 16;\n" ::"r"(sb), "l"(gb));
        }
        asm volatile("cp.async.commit_group;\n");
    };

    load_tile(0, 0);

    for (int kt = 0; kt < KT; kt++) {
        int buf = kt & 1;
        if (kt + 1 < KT) {
            load_tile(kt + 1, buf ^ 1);
            asm volatile("cp.async.wait_group 1;\n");
        } else {
            asm volatile("cp.async.wait_group 0;\n");
        }
        __syncthreads();
        __nv_bfloat16* sAb = sA + buf * BM * BK;
        __nv_bfloat16* sBb = sB + buf * BN * BK;
#pragma unroll
        for (int ks = 0; ks < BK / 16; ks++) {
            uint32_t af[4][4];
#pragma unroll
            for (int mt = 0; mt < 4; mt++) {
                int j = lane >> 3;
                int r = wm + mt * 16 + ((j & 1) << 3) + (lane & 7);
                int unit = (ks * 2 + (j >> 1)) ^ (r & 7);
                uint32_t addr = smem_u32(sAb + r * BK + unit * 8);
                asm volatile("ldmatrix.sync.aligned.m8n8.x4.shared.b16 {%0,%1,%2,%3}, [%4];\n"
                             : "=r"(af[mt][0]), "=r"(af[mt][1]), "=r"(af[mt][2]), "=r"(af[mt][3])
                             : "r"(addr));
            }
            uint32_t bfr[4][2];
#pragma unroll
            for (int nt2 = 0; nt2 < 2; nt2++) {
                int j = lane >> 3;
                int r = wn + nt2 * 16 + ((j >> 1) << 3) + (lane & 7);
                int unit = (ks * 2 + (j & 1)) ^ (r & 7);
                uint32_t addr = smem_u32(sBb + r * BK + unit * 8);
                uint32_t b0, b1, b2, b3;
                asm volatile("ldmatrix.sync.aligned.m8n8.x4.shared.b16 {%0,%1,%2,%3}, [%4];\n"
                             : "=r"(b0), "=r"(b1), "=r"(b2), "=r"(b3) : "r"(addr));
                bfr[nt2 * 2][0] = b0; bfr[nt2 * 2][1] = b1;
                bfr[nt2 * 2 + 1][0] = b2; bfr[nt2 * 2 + 1][1] = b3;
            }
#pragma unroll
            for (int mt = 0; mt < 4; mt++)
#pragma unroll
                for (int nt = 0; nt < 4; nt++) {
                    asm volatile(
                        "mma.sync.aligned.m16n8k16.row.col.f32.bf16.bf16.f32 "
                        "{%0,%1,%2,%3}, {%4,%5,%6,%7}, {%8,%9}, {%0,%1,%2,%3};\n"
                        : "+f"(acc[mt][nt][0]), "+f"(acc[mt][nt][1]),
                          "+f"(acc[mt][nt][2]), "+f"(acc[mt][nt][3])
                        : "r"(af[mt][0]), "r"(af[mt][1]), "r"(af[mt][2]), "r"(af[mt][3]),
                          "r"(bfr[nt][0]), "r"(bfr[nt][1]));
                }
        }
        __syncthreads();
    }

#pragma unroll
    for (int mt = 0; mt < 4; mt++) {
#pragma unroll
        for (int nt = 0; nt < 4; nt++) {
            int row0 = bm + wm + mt * 16 + (lane >> 2);
            int col = bn + wn + nt * 8 + ((lane & 3) << 1);
            float b0 = bias[col], b1 = bias[col + 1];
            float v00 = acc[mt][nt][0] + b0, v01 = acc[mt][nt][1] + b1;
            float v10 = acc[mt][nt][2] + b0, v11 = acc[mt][nt][3] + b1;
            if (OUT_MODE == 1) {
                const float* r0p = res + (size_t)row0 * N + col;
                const float* r1p = res + (size_t)(row0 + 8) * N + col;
                v00 += r0p[0]; v01 += r0p[1]; v10 += r1p[0]; v11 += r1p[1];
            }
            if (OUT_MODE == 2) {
                __nv_bfloat16* C = (__nv_bfloat16*)Cout;
                *(__nv_bfloat162*)(C + (size_t)row0 * N + col) = __floats2bfloat162_rn(v00, v01);
                *(__nv_bfloat162*)(C + (size_t)(row0 + 8) * N + col) = __floats2bfloat162_rn(v10, v11);
            } else {
                float* C = (float*)Cout;
                *(float2*)(C + (size_t)row0 * N + col) = make_float2(v00, v01);
                *(float2*)(C + (size_t)(row0 + 8) * N + col) = make_float2(v10, v11);
            }
        }
    }
}

// ---------------- final: out = x2 + silu(a1) * a2 ----------------
__global__ void k_final(const float* __restrict__ x2, const float* __restrict__ a,
                        const float* __restrict__ b, float* __restrict__ out, int n) {
    int i = blockIdx.x * blockDim.x + threadIdx.x;
    if (i < n) {
        float av = a[i];
        float s = av / (1.f + __expf(-av));
        out[i] = x2[i] + s * b[i];
    }
}

// ---------------- orchestration ----------------
extern "C" void kernel_launch(void* const* d_in, const int* in_sizes, int n_in,
                              void* d_out, int out_size) {
    const float* x      = (const float*)d_in[0];
    const float* wq     = (const float*)d_in[1];
    const float* bq     = (const float*)d_in[2];
    const float* wk     = (const float*)d_in[3];
    const float* bk     = (const float*)d_in[4];
    const float* wv     = (const float*)d_in[5];
    const float* bv     = (const float*)d_in[6];
    const float* wo     = (const float*)d_in[7];
    const float* bo     = (const float*)d_in[8];
    const float* scale1 = (const float*)d_in[9];
    const float* scale2 = (const float*)d_in[10];
    const float* w_in   = (const float*)d_in[11];
    const float* b_in   = (const float*)d_in[12];
    const float* w1     = (const float*)d_in[13];
    const float* b1     = (const float*)d_in[14];
    const float* w2     = (const float*)d_in[15];
    const float* b2     = (const float*)d_in[16];
    float* out = (float*)d_out;

    __nv_bfloat16 *Wqkv, *Wo, *Win, *W1, *W2, *h, *ctx, *hid;
    float *bqkv, *x1, *qkv, *x2, *a1, *a2;
    cudaGetSymbolAddress((void**)&Wqkv, g_Wqkv);
    cudaGetSymbolAddress((void**)&Wo,   g_Wo);
    cudaGetSymbolAddress((void**)&Win,  g_Win);
    cudaGetSymbolAddress((void**)&W1,   g_W1);
    cudaGetSymbolAddress((void**)&W2,   g_W2);
    cudaGetSymbolAddress((void**)&bqkv, g_bqkv);
    cudaGetSymbolAddress((void**)&x1,   g_x1);
    cudaGetSymbolAddress((void**)&h,    g_h);
    cudaGetSymbolAddress((void**)&qkv,  g_qkv);
    cudaGetSymbolAddress((void**)&ctx,  g_ctx);
    cudaGetSymbolAddress((void**)&x2,   g_x2);
    cudaGetSymbolAddress((void**)&hid,  g_hid);
    cudaGetSymbolAddress((void**)&a1,   g_a1);
    cudaGetSymbolAddress((void**)&a2,   g_a2);

    cudaFuncSetAttribute(gemm_bf16<0>, cudaFuncAttributeMaxDynamicSharedMemorySize, SMEM_BYTES);
    cudaFuncSetAttribute(gemm_bf16<1>, cudaFuncAttributeMaxDynamicSharedMemorySize, SMEM_BYTES);
    cudaFuncSetAttribute(gemm_bf16<2>, cudaFuncAttributeMaxDynamicSharedMemorySize, SMEM_BYTES);

    // weight conversion fp32 -> bf16 (QKV packed)
    const int n4_dd = (DIM * DIM) / 4;       // 1048576
    const int n4_fd = (FFN * DIM) / 4;       // 4194304
    k_cvt<<<(n4_dd + 255) / 256, 256>>>(wq, Wqkv, n4_dd);
    k_cvt<<<(n4_dd + 255) / 256, 256>>>(wk, Wqkv + (size_t)DIM * DIM, n4_dd);
    k_cvt<<<(n4_dd + 255) / 256, 256>>>(wv, Wqkv + (size_t)2 * DIM * DIM, n4_dd);
    k_cvt<<<(n4_dd + 255) / 256, 256>>>(wo, Wo, n4_dd);
    k_cvt<<<(n4_fd + 255) / 256, 256>>>(w_in, Win, n4_fd);
    k_cvt<<<(n4_fd + 255) / 256, 256>>>(w1, W1, n4_fd);
    k_cvt<<<(n4_fd + 255) / 256, 256>>>(w2, W2, n4_fd);
    cudaMemcpyAsync(bqkv, bq, DIM * sizeof(float), cudaMemcpyDeviceToDevice);
    cudaMemcpyAsync(bqkv + DIM, bk, DIM * sizeof(float), cudaMemcpyDeviceToDevice);
    cudaMemcpyAsync(bqkv + 2 * DIM, bv, DIM * sizeof(float), cudaMemcpyDeviceToDevice);

    // x1 = x + rotary ; h = rmsnorm(x1, scale1)
    k_rot_rms<<<MROWS, 256>>>(x, scale1, x1, h);
    // qkv = h @ Wqkv^T + bqkv
    gemm_bf16<0><<<dim3(QKV_N / BN, MROWS / BM), 256, SMEM_BYTES>>>(
        h, Wqkv, bqkv, nullptr, qkv, MROWS, QKV_N, DIM);
    // per-token head attention
    k_attn<<<MROWS, 256>>>(qkv, ctx);
    // x2 = x1 + ctx @ Wo^T + bo
    gemm_bf16<1><<<dim3(DIM / BN, MROWS / BM), 256, SMEM_BYTES>>>(
        ctx, Wo, bo, x1, x2, MROWS, DIM, DIM);
    // h = rmsnorm(x2, scale2)
    k_rms<<<MROWS, 256>>>(x2, scale2, h);
    // hidden = h @ Win^T + b_in   (bf16 out)
    gemm_bf16<2><<<dim3(FFN / BN, MROWS / BM), 256, SMEM_BYTES>>>(
        h, Win, b_in, nullptr, hid, MROWS, FFN, DIM);
    // a1 = hidden @ W1^T + b1 ; a2 = hidden @ W2^T + b2
    gemm_bf16<0><<<dim3(DIM / BN, MROWS / BM), 256, SMEM_BYTES>>>(
        hid, W1, b1, nullptr, a1, MROWS, DIM, FFN);
    gemm_bf16<0><<<dim3(DIM / BN, MROWS / BM), 256, SMEM_BYTES>>>(
        hid, W2, b2, nullptr, a2, MROWS, DIM, FFN);
    // out = x2 + silu(a1)*a2
    k_final<<<(MROWS * DIM + 255) / 256, 256>>>(x2, a1, a2, out, MROWS * DIM);
}